// round 3
// baseline (speedup 1.0000x reference)
#include <cuda_runtime.h>
#include <math.h>

#define BB 16
#define AA 3
#define SDIM 80
#define NC 80
#define NT 32
#define SSP (SDIM * SDIM)             // 6400
#define CH (5 + NC)                   // 85
#define CELLS (BB * AA * SSP)         // 307200
#define NTHR 512
#define NBLK (CELLS / 4 / NTHR)       // 150 (one float4 per thread)
#define EPSF 1e-7f
#define IMG 640.0f
#define STRIDEF 8.0f

// Per-block partial sums, written by plain stores every call (no zeroing,
// no atomics, no state carried across graph replays).
__device__ float g_partial[NBLK];

__device__ __forceinline__ float softplusf(float x) {
    return fmaxf(x, 0.0f) + log1pf(__expf(-fabsf(x)));
}
__device__ __forceinline__ float sigmoidf(float x) {
    return 1.0f / (1.0f + __expf(-x));
}

// Block-wide float sum; result valid in thread 0. Ends with __syncthreads so
// the shared buffer can be reused immediately.
__device__ __forceinline__ float block_sum(float v, float* red, int tid) {
    #pragma unroll
    for (int o = 16; o > 0; o >>= 1) v += __shfl_down_sync(0xffffffffu, v, o);
    if ((tid & 31) == 0) red[tid >> 5] = v;
    __syncthreads();
    if (tid < 32) {
        v = (tid < (NTHR >> 5)) ? red[tid] : 0.0f;
        #pragma unroll
        for (int o = 8; o > 0; o >>= 1) v += __shfl_down_sync(0xffffffffu, v, o);
    }
    __syncthreads();
    return v;
}

// ───────────────────────── Kernel 1: conf softplus partials ────────────────
__global__ void __launch_bounds__(NTHR)
k_conf(const float* __restrict__ preds)
{
    __shared__ float red[16];
    int tid = threadIdx.x;
    int idx = blockIdx.x * NTHR + tid;          // 0..76799 (float4 units)
    int plane = idx / (SSP / 4);                // b*3 + a (48 planes × 1600 f4)
    int off4  = idx - plane * (SSP / 4);
    int b = plane / AA, a = plane - AA * b;
    const float4* p4 = (const float4*)(preds +
        ((size_t)(b * (AA * CH) + a * CH + 4)) * SSP);
    float4 v = p4[off4];
    float s = softplusf(v.x) + softplusf(v.y) + softplusf(v.z) + softplusf(v.w);
    float bsum = block_sum(s, red, tid);
    if (tid == 0) g_partial[blockIdx.x] = bsum;
}

// ───────────────────────── Kernel 2: targets + finalize ────────────────────
__device__ __forceinline__ void assign_target(
    const float* __restrict__ tbox, const float* aw, const float* ah,
    int b, int m, int& a, int& gi, int& gj)
{
    const float* p = tbox + (size_t)(b * NT + m) * 4;
    float x = p[0], y = p[1], w = p[2], h = p[3];
    gi = min(max((int)floorf(x * (float)SDIM), 0), SDIM - 1);
    gj = min(max((int)floorf(y * (float)SDIM), 0), SDIM - 1);
    float tw = w * IMG, th = h * IMG;
    float best = -1.0f; a = 0;
    #pragma unroll
    for (int k = 0; k < AA; k++) {
        float inter = fminf(tw, aw[k]) * fminf(th, ah[k]);
        float un = tw * th + aw[k] * ah[k] - inter;
        float r = inter / un;
        if (r > best) { best = r; a = k; }     // first-max wins (jnp.argmax)
    }
}

__device__ __forceinline__ float ciou_f(
    float px1, float py1, float px2, float py2,
    float tx1, float ty1, float tx2, float ty2)
{
    float iw = fmaxf(fminf(px2, tx2) - fmaxf(px1, tx1), 0.0f);
    float ih = fmaxf(fminf(py2, ty2) - fmaxf(py1, ty1), 0.0f);
    float inter = iw * ih;
    float pa = fmaxf(px2 - px1, 0.0f) * fmaxf(py2 - py1, 0.0f);
    float ta = fmaxf(tx2 - tx1, 0.0f) * fmaxf(ty2 - ty1, 0.0f);
    float un = pa + ta - inter + EPSF;
    float iou = inter / un;
    float dx = 0.5f * (px1 + px2) - 0.5f * (tx1 + tx2);
    float dy = 0.5f * (py1 + py2) - 0.5f * (ty1 + ty2);
    float cd = dx * dx + dy * dy;
    float ew = fmaxf(px2, tx2) - fminf(px1, tx1);
    float eh = fmaxf(py2, ty2) - fminf(py1, ty1);
    float ed = ew * ew + eh * eh + EPSF;
    float pw = fmaxf(px2 - px1, EPSF);
    float ph = fmaxf(py2 - py1, EPSF);
    float tw = fmaxf(tx2 - tx1, EPSF);
    float th = fmaxf(ty2 - ty1, EPSF);
    float da = atanf(tw / th) - atanf(pw / ph);
    float v = (4.0f / ((float)M_PI * (float)M_PI)) * da * da;
    float alpha = v / (1.0f - iou + v + EPSF);
    return iou - cd / ed - alpha * v;
}

__global__ void __launch_bounds__(NTHR)
k_targets(const float* __restrict__ preds,
          const float* __restrict__ anchors,
          const int* __restrict__ tcls,
          const float* __restrict__ tbox,
          float* __restrict__ out)
{
    __shared__ float red[16];
    __shared__ int   s_cell[NTHR];

    int tid = threadIdx.x;

    // conf-sum partials (stream-ordered after k_conf)
    float pconf = (tid < NBLK) ? g_partial[tid] : 0.0f;

    float aw[AA], ah[AA];
    #pragma unroll
    for (int k = 0; k < AA; k++) { aw[k] = anchors[2 * k]; ah[k] = anchors[2 * k + 1]; }

    int tb = tid / NT, tn = tid - tb * NT;     // 512 = B*N exactly
    int ta, gi, gj;
    assign_target(tbox, aw, ah, tb, tn, ta, gi, gj);
    int cell = ((tb * AA + ta) * SDIM + gj) * SDIM + gi;
    s_cell[tid] = cell;
    __syncthreads();

    // owner = lowest tid in this batch mapping to this cell
    bool owner = true;
    for (int m = tb * NT; m < tb * NT + tn; m++)
        if (s_cell[m] == cell) { owner = false; break; }

    float f_ciou = 0.f, f_bce = 0.f, f_sp = 0.f, f_cls = 0.f, f_cnt = 0.f;

    if (owner) {
        // rescan this batch: class-set union, box last-write-wins (JAX .at.set)
        unsigned clsbits[3] = {0u, 0u, 0u};
        float wx1 = 0.f, wy1 = 0.f, wx2 = 0.f, wy2 = 0.f;
        for (int m = 0; m < NT; m++) {
            if (s_cell[tb * NT + m] == cell) {
                int c = tcls[tb * NT + m];
                clsbits[c >> 5] |= (1u << (c & 31));
                const float* p = tbox + (size_t)(tb * NT + m) * 4;
                float cx = p[0] * IMG, cy = p[1] * IMG;
                float tw = p[2] * IMG, th = p[3] * IMG;
                wx1 = cx - 0.5f * tw; wy1 = cy - 0.5f * th;
                wx2 = cx + 0.5f * tw; wy2 = cy + 0.5f * th;
            }
        }

        size_t base = ((size_t)tb * (AA * CH) + (size_t)ta * CH) * SSP
                      + (size_t)gj * SDIM + gi;
        float p0 = preds[base];
        float p1 = preds[base + (size_t)SSP];
        float p2 = preds[base + (size_t)2 * SSP];
        float p3 = preds[base + (size_t)3 * SSP];
        float pc = preds[base + (size_t)4 * SSP];

        float pcx = (sigmoidf(p0) + (float)gi) * STRIDEF;
        float pcy = (sigmoidf(p1) + (float)gj) * STRIDEF;
        float pw = aw[ta] * __expf(p2);
        float ph = ah[ta] * __expf(p3);

        f_ciou = ciou_f(pcx - 0.5f * pw, pcy - 0.5f * ph,
                        pcx + 0.5f * pw, pcy + 0.5f * ph,
                        wx1, wy1, wx2, wy2);
        f_sp  = softplusf(pc);
        f_bce = f_sp - pc;
        f_cnt = 1.0f;

        float cs = 0.0f;
        #pragma unroll 8
        for (int c = 0; c < NC; c++) {
            float l = preds[base + (size_t)(5 + c) * SSP];
            float tgt = (float)((clsbits[c >> 5] >> (c & 31)) & 1u);
            cs += softplusf(l) - l * tgt;
        }
        f_cls = cs;
    }

    float r_conf = block_sum(pconf, red, tid);
    float r_ciou = block_sum(f_ciou, red, tid);
    float r_bce  = block_sum(f_bce,  red, tid);
    float r_sp   = block_sum(f_sp,   red, tid);
    float r_cls  = block_sum(f_cls,  red, tid);
    float r_cnt  = block_sum(f_cnt,  red, tid);

    if (tid == 0) {
        double nobj = (double)r_cnt;
        double dn_obj   = fmax(nobj, 1.0);
        double dn_noobj = fmax((double)CELLS - nobj, 1.0);
        double dn_cls   = fmax(nobj * (double)NC, 1.0);

        double loss_ciou       = 1.0 - (double)r_ciou / dn_obj;
        double loss_conf_obj   = (double)r_bce / dn_obj;
        double loss_conf_noobj = ((double)r_conf - (double)r_sp) / dn_noobj;
        double loss_cls        = (double)r_cls / dn_cls;

        out[0] = (float)(loss_ciou + loss_conf_obj
                         + 0.5 * loss_conf_noobj + loss_cls);
    }
}

extern "C" void kernel_launch(void* const* d_in, const int* in_sizes, int n_in,
                              void* d_out, int out_size)
{
    const float* preds   = (const float*)d_in[0];
    const float* anchors = (const float*)d_in[1];
    const int*   tcls    = (const int*)d_in[2];
    const float* tbox    = (const float*)d_in[3];

    k_conf<<<NBLK, NTHR>>>(preds);
    k_targets<<<1, NTHR>>>(preds, anchors, tcls, tbox, (float*)d_out);
}

// round 4
// speedup vs baseline: 45.4675x; 45.4675x over previous
#include <cuda_runtime.h>
#include <math.h>

#define BB 16
#define AA 3
#define SDIM 80
#define NC 80
#define NT 32
#define SSP (SDIM * SDIM)             // 6400
#define CH (5 + NC)                   // 85
#define CELLS (BB * AA * SSP)         // 307200
#define NTARG (BB * NT)               // 512
#define CONF_THR 512
#define CONF_BLK (CELLS / 4 / CONF_THR)   // 150
#define OBJ_STRIDE 8                  // floats per target slot (padded)
#define EPSF 1e-7f
#define IMG 640.0f
#define STRIDEF 8.0f

// Scratch: rewritten by plain stores on every call (no zeroing kernel,
// no atomics to global, no state across graph replays).
__device__ float g_confpart[CONF_BLK];
__device__ float g_objout[NTARG * OBJ_STRIDE];

__device__ __forceinline__ float softplusf(float x) {
    return fmaxf(x, 0.0f) + log1pf(__expf(-fabsf(x)));
}
__device__ __forceinline__ float sigmoidf(float x) {
    return 1.0f / (1.0f + __expf(-x));
}

__device__ __forceinline__ void assign_target(
    const float* __restrict__ tbox, const float* aw, const float* ah,
    int b, int m, int& a, int& gi, int& gj)
{
    const float* p = tbox + (size_t)(b * NT + m) * 4;
    float x = p[0], y = p[1], w = p[2], h = p[3];
    gi = min(max((int)floorf(x * (float)SDIM), 0), SDIM - 1);
    gj = min(max((int)floorf(y * (float)SDIM), 0), SDIM - 1);
    float tw = w * IMG, th = h * IMG;
    float best = -1.0f; a = 0;
    #pragma unroll
    for (int k = 0; k < AA; k++) {
        float inter = fminf(tw, aw[k]) * fminf(th, ah[k]);
        float un = tw * th + aw[k] * ah[k] - inter;
        float r = inter / un;
        if (r > best) { best = r; a = k; }   // first-max wins (jnp.argmax)
    }
}

__device__ __forceinline__ float ciou_f(
    float px1, float py1, float px2, float py2,
    float tx1, float ty1, float tx2, float ty2)
{
    float iw = fmaxf(fminf(px2, tx2) - fmaxf(px1, tx1), 0.0f);
    float ih = fmaxf(fminf(py2, ty2) - fmaxf(py1, ty1), 0.0f);
    float inter = iw * ih;
    float pa = fmaxf(px2 - px1, 0.0f) * fmaxf(py2 - py1, 0.0f);
    float ta = fmaxf(tx2 - tx1, 0.0f) * fmaxf(ty2 - ty1, 0.0f);
    float un = pa + ta - inter + EPSF;
    float iou = inter / un;
    float dx = 0.5f * (px1 + px2) - 0.5f * (tx1 + tx2);
    float dy = 0.5f * (py1 + py2) - 0.5f * (ty1 + ty2);
    float cd = dx * dx + dy * dy;
    float ew = fmaxf(px2, tx2) - fminf(px1, tx1);
    float eh = fmaxf(py2, ty2) - fminf(py1, ty1);
    float ed = ew * ew + eh * eh + EPSF;
    float pw = fmaxf(px2 - px1, EPSF);
    float ph = fmaxf(py2 - py1, EPSF);
    float tw = fmaxf(tx2 - tx1, EPSF);
    float th = fmaxf(ty2 - ty1, EPSF);
    float da = atanf(tw / th) - atanf(pw / ph);
    float v = (4.0f / ((float)M_PI * (float)M_PI)) * da * da;
    float alpha = v / (1.0f - iou + v + EPSF);
    return iou - cd / ed - alpha * v;
}

// ───────────── Kernel 1: conf softplus partial sums (wide, coalesced) ──────
__global__ void __launch_bounds__(CONF_THR)
k_conf(const float* __restrict__ preds)
{
    __shared__ float red[16];
    int tid = threadIdx.x;
    int idx = blockIdx.x * CONF_THR + tid;     // float4 units, 0..76799
    int plane = idx / (SSP / 4);               // b*3 + a (48 planes × 1600)
    int off4  = idx - plane * (SSP / 4);
    int b = plane / AA, a = plane - AA * b;
    const float4* p4 = (const float4*)(preds +
        ((size_t)(b * (AA * CH) + a * CH + 4)) * SSP);
    float4 v = p4[off4];
    float s = softplusf(v.x) + softplusf(v.y) + softplusf(v.z) + softplusf(v.w);

    #pragma unroll
    for (int o = 16; o > 0; o >>= 1) s += __shfl_down_sync(0xffffffffu, s, o);
    if ((tid & 31) == 0) red[tid >> 5] = s;
    __syncthreads();
    if (tid < 32) {
        s = (tid < (CONF_THR >> 5)) ? red[tid] : 0.0f;
        #pragma unroll
        for (int o = 8; o > 0; o >>= 1) s += __shfl_down_sync(0xffffffffu, s, o);
        if (tid == 0) g_confpart[blockIdx.x] = s;
    }
}

// ───────────── Kernel 2: one block per target (wide obj-cell work) ─────────
__global__ void __launch_bounds__(128)
k_obj(const float* __restrict__ preds,
      const float* __restrict__ anchors,
      const int* __restrict__ tcls,
      const float* __restrict__ tbox)
{
    __shared__ int s_cell[NT];
    __shared__ int s_cls[NT];
    __shared__ unsigned s_bits[3];
    __shared__ int s_lastm;
    __shared__ float s_red[4];

    int t = blockIdx.x;                 // target index 0..511
    int b = t / NT, n = t - b * NT;
    int tid = threadIdx.x;

    float aw[AA], ah[AA];
    #pragma unroll
    for (int k = 0; k < AA; k++) { aw[k] = anchors[2 * k]; ah[k] = anchors[2 * k + 1]; }

    if (tid < NT) {
        int a, gi, gj;
        assign_target(tbox, aw, ah, b, tid, a, gi, gj);
        s_cell[tid] = ((b * AA + a) * SDIM + gj) * SDIM + gi;
        s_cls[tid]  = tcls[b * NT + tid];
    }
    if (tid == 0) { s_bits[0] = s_bits[1] = s_bits[2] = 0u; s_lastm = -1; }
    __syncthreads();

    int cell = s_cell[n];
    // block-uniform owner test: owner = smallest m in batch with this cell
    bool owner = true;
    for (int m = 0; m < n; m++)
        if (s_cell[m] == cell) { owner = false; break; }

    float* slot = g_objout + (size_t)t * OBJ_STRIDE;
    if (!owner) {
        if (tid == 0) {
            slot[0] = 0.f; slot[1] = 0.f; slot[2] = 0.f; slot[3] = 0.f; slot[4] = 0.f;
        }
        return;                          // uniform exit for the whole block
    }

    // class-set union + last-write-wins box index (shared atomics, cheap)
    if (tid < NT && s_cell[tid] == cell) {
        int c = s_cls[tid];
        atomicOr(&s_bits[c >> 5], 1u << (c & 31));
        atomicMax(&s_lastm, tid);
    }
    __syncthreads();

    // decode cell → (a, gj, gi)
    int gi = cell % SDIM;
    int gj = (cell / SDIM) % SDIM;
    int a  = (cell / SSP) % AA;
    size_t base = ((size_t)b * (AA * CH) + (size_t)a * CH) * SSP
                  + (size_t)gj * SDIM + gi;

    // class BCE: one logit per thread (80 parallel loads, one round-trip)
    float cs = 0.0f;
    if (tid < NC) {
        float l = preds[base + (size_t)(5 + tid) * SSP];
        float tgt = (float)((s_bits[tid >> 5] >> (tid & 31)) & 1u);
        cs = softplusf(l) - l * tgt;
    }
    #pragma unroll
    for (int o = 16; o > 0; o >>= 1) cs += __shfl_down_sync(0xffffffffu, cs, o);
    if ((tid & 31) == 0) s_red[tid >> 5] = cs;
    __syncthreads();

    if (tid == 0) {
        float cls_sum = s_red[0] + s_red[1] + s_red[2] + s_red[3];

        float p0 = preds[base];
        float p1 = preds[base + (size_t)SSP];
        float p2 = preds[base + (size_t)2 * SSP];
        float p3 = preds[base + (size_t)3 * SSP];
        float pc = preds[base + (size_t)4 * SSP];

        const float* tp = tbox + (size_t)(b * NT + s_lastm) * 4;
        float cx = tp[0] * IMG, cy = tp[1] * IMG;
        float tw = tp[2] * IMG, th = tp[3] * IMG;
        float wx1 = cx - 0.5f * tw, wy1 = cy - 0.5f * th;
        float wx2 = cx + 0.5f * tw, wy2 = cy + 0.5f * th;

        float pcx = (sigmoidf(p0) + (float)gi) * STRIDEF;
        float pcy = (sigmoidf(p1) + (float)gj) * STRIDEF;
        float pw = aw[a] * __expf(p2);
        float ph = ah[a] * __expf(p3);

        float ciou = ciou_f(pcx - 0.5f * pw, pcy - 0.5f * ph,
                            pcx + 0.5f * pw, pcy + 0.5f * ph,
                            wx1, wy1, wx2, wy2);
        float sp = softplusf(pc);

        slot[0] = 1.0f;          // obj count
        slot[1] = ciou;
        slot[2] = sp - pc;       // bce(conf, 1)
        slot[3] = sp;            // softplus correction for noobj term
        slot[4] = cls_sum;
    }
}

// ───────────── Kernel 3: light finalize (small reads only) ─────────────────
__global__ void __launch_bounds__(NTARG)
k_final(float* __restrict__ out)
{
    __shared__ float red[16];
    int tid = threadIdx.x;

    float conf = (tid < CONF_BLK) ? g_confpart[tid] : 0.0f;

    const float4* po = (const float4*)g_objout;
    float4 u0 = po[tid * 2];
    float4 u1 = po[tid * 2 + 1];
    float cnt = u0.x, ciou = u0.y, bce = u0.z, sp = u0.w, cls = u1.x;

    float vals[6] = { conf, cnt, ciou, bce, sp, cls };
    float sums[6];
    #pragma unroll
    for (int i = 0; i < 6; i++) {
        float v = vals[i];
        #pragma unroll
        for (int o = 16; o > 0; o >>= 1) v += __shfl_down_sync(0xffffffffu, v, o);
        if ((tid & 31) == 0) red[tid >> 5] = v;
        __syncthreads();
        if (tid < 32) {
            v = (tid < (NTARG >> 5)) ? red[tid] : 0.0f;
            #pragma unroll
            for (int o = 8; o > 0; o >>= 1) v += __shfl_down_sync(0xffffffffu, v, o);
        }
        __syncthreads();
        sums[i] = v;             // valid in tid 0
    }

    if (tid == 0) {
        double nobj = (double)sums[1];
        double dn_obj   = fmax(nobj, 1.0);
        double dn_noobj = fmax((double)CELLS - nobj, 1.0);
        double dn_cls   = fmax(nobj * (double)NC, 1.0);

        double loss_ciou       = 1.0 - (double)sums[2] / dn_obj;
        double loss_conf_obj   = (double)sums[3] / dn_obj;
        double loss_conf_noobj = ((double)sums[0] - (double)sums[4]) / dn_noobj;
        double loss_cls        = (double)sums[5] / dn_cls;

        out[0] = (float)(loss_ciou + loss_conf_obj
                         + 0.5 * loss_conf_noobj + loss_cls);
    }
}

extern "C" void kernel_launch(void* const* d_in, const int* in_sizes, int n_in,
                              void* d_out, int out_size)
{
    const float* preds   = (const float*)d_in[0];
    const float* anchors = (const float*)d_in[1];
    const int*   tcls    = (const int*)d_in[2];
    const float* tbox    = (const float*)d_in[3];

    k_conf<<<CONF_BLK, CONF_THR>>>(preds);
    k_obj<<<NTARG, 128>>>(preds, anchors, tcls, tbox);
    k_final<<<1, NTARG>>>((float*)d_out);
}